// round 3
// baseline (speedup 1.0000x reference)
#include <cuda_runtime.h>
#include <cstdint>

#define NBATCH   2048
#define CEM_S    1000
#define CEM_NE   100
#define CEM_NI   10
#define HID      128
#define KT       32                   // k-tile for smem
#define TOTAL    (NBATCH * CEM_S)     // 2,048,000
#define INIT_SIG 10.0f

// ---------------- device scratch (no allocations allowed) ----------------
__device__ float g_mu[NBATCH];
__device__ float g_sigma[NBATCH];
__device__ float g_y[TOTAL];
__device__ float g_fx[TOTAL];

// ---------------- threefry-2x32 (exact JAX) ----------------
static __host__ __device__ __forceinline__ uint32_t rotl32(uint32_t v, uint32_t d) {
    return (v << d) | (v >> (32u - d));
}

static __host__ __device__ __forceinline__ void threefry2x32(
    uint32_t k0, uint32_t k1, uint32_t& x0, uint32_t& x1)
{
    uint32_t ks0 = k0, ks1 = k1, ks2 = k0 ^ k1 ^ 0x1BD11BDAu;
    x0 += ks0; x1 += ks1;
#define TF_R(r) { x0 += x1; x1 = rotl32(x1, r); x1 ^= x0; }
    TF_R(13) TF_R(15) TF_R(26) TF_R(6)   x0 += ks1; x1 += ks2 + 1u;
    TF_R(17) TF_R(29) TF_R(16) TF_R(24)  x0 += ks2; x1 += ks0 + 2u;
    TF_R(13) TF_R(15) TF_R(26) TF_R(6)   x0 += ks0; x1 += ks1 + 3u;
    TF_R(17) TF_R(29) TF_R(16) TF_R(24)  x0 += ks1; x1 += ks2 + 4u;
    TF_R(13) TF_R(15) TF_R(26) TF_R(6)   x0 += ks2; x1 += ks0 + 5u;
#undef TF_R
}

// partitionable-mode random bits for 32-bit: element i -> XOR-fold of cipher pair
__device__ __forceinline__ uint32_t tf_bits32(uint32_t k0, uint32_t k1, uint32_t idx) {
    uint32_t x0 = 0u, x1 = idx;     // counter = uint64 idx (hi=0 for idx < 2^32)
    threefry2x32(k0, k1, x0, x1);
    return x0 ^ x1;
}

// bits -> standard normal, matching jax.random.normal (uniform(-1+ulp,1) -> sqrt2*erfinv)
__device__ __forceinline__ float bits_to_normal(uint32_t bits) {
    float f = __uint_as_float((bits >> 9) | 0x3f800000u) - 1.0f;   // [0,1)
    const float lo = -0.99999994f;                                  // nextafter(-1,0)
    float u = fmaxf(lo, f * 2.0f + lo);                             // (hi-lo) rounds to 2.0f
    // XLA ErfInv f32 polynomial
    float w = -log1pf(-u * u);
    float p;
    if (w < 5.0f) {
        w -= 2.5f;
        p = 2.81022636e-08f;
        p = fmaf(p, w, 3.43273939e-07f);
        p = fmaf(p, w, -3.5233877e-06f);
        p = fmaf(p, w, -4.39150654e-06f);
        p = fmaf(p, w, 0.00021858087f);
        p = fmaf(p, w, -0.00125372503f);
        p = fmaf(p, w, -0.00417768164f);
        p = fmaf(p, w, 0.246640727f);
        p = fmaf(p, w, 1.50140941f);
    } else {
        w = sqrtf(w) - 3.0f;
        p = -0.000200214257f;
        p = fmaf(p, w, 0.000100950558f);
        p = fmaf(p, w, 0.00134934322f);
        p = fmaf(p, w, -0.00367342844f);
        p = fmaf(p, w, 0.00573950773f);
        p = fmaf(p, w, -0.0076224613f);
        p = fmaf(p, w, 0.00943887047f);
        p = fmaf(p, w, 1.00167406f);
        p = fmaf(p, w, 2.83297682f);
    }
    return 1.4142135623730951f * (p * u);   // float32(sqrt(2)) * erfinv(u)
}

// ---------------- packed f32x2 helpers ----------------
__device__ __forceinline__ void unpack2(unsigned long long v, float& lo, float& hi) {
    asm("mov.b64 {%0, %1}, %2;" : "=f"(lo), "=f"(hi) : "l"(v));
}
__device__ __forceinline__ void fma2(unsigned long long& d, unsigned long long a, unsigned long long b) {
    asm("fma.rn.f32x2 %0, %1, %2, %0;" : "+l"(d) : "l"(a), "l"(b));
}

// ---------------- init ----------------
__global__ void init_kernel() {
    int i = blockIdx.x * blockDim.x + threadIdx.x;
    if (i < NBATCH) { g_mu[i] = 0.0f; g_sigma[i] = INIT_SIG; }
}

// ---------------- fused sample + energy kernel ----------------
// One block = 128 candidates. 256 threads, 2 CTAs/SM.
// Dynamic smem (48KB): w2d = KT x 128 duplicated (w,w) pairs (32KB), h1t = KT x 128 (16KB).
// 'red' (128x17 floats) aliases the dynamic buffer after the GEMM completes.
__global__ void __launch_bounds__(256, 2) energy_kernel(
    uint32_t k0, uint32_t k1,
    const float* __restrict__ x,  const float* __restrict__ W1, const float* __restrict__ b1,
    const float* __restrict__ W2, const float* __restrict__ b2,
    const float* __restrict__ W3, const float* __restrict__ b3)
{
    extern __shared__ float dyn[];
    float2* w2d = reinterpret_cast<float2*>(dyn);       // [KT*128] (w,w) pairs
    float*  h1t = dyn + 2 * KT * 128;                   // [KT*128] : h1t[k][m]
    float*  red = dyn;                                  // alias post-GEMM: [128][17]

    __shared__ float sy[128], sxv[128];
    __shared__ float sW1a[HID], sW1b[HID], sb1[HID], sb2[HID], sW3[HID];
    __shared__ float sb3;

    const int tid = threadIdx.x;
    const int g0  = blockIdx.x * 128;

    // stage small weights
    if (tid < HID) {
        sW1a[tid] = W1[tid];
        sW1b[tid] = W1[HID + tid];
        sb1[tid]  = b1[tid];
        sb2[tid]  = b2[tid];
        sW3[tid]  = W3[tid];
    }
    if (tid == 0) sb3 = b3[0];

    // generate candidates: eps via threefry (partitionable), Ys = mu + sigma*eps
    if (tid < 128) {
        int g = g0 + tid;                   // flat (NB, CEM_S) row-major index
        int b = g / CEM_S;
        float eps = bits_to_normal(tf_bits32(k0, k1, (uint32_t)g));
        float yv  = g_mu[b] + g_sigma[b] * eps;
        sy[tid]  = yv;
        sxv[tid] = x[b];
        g_y[g]   = yv;
    }
    __syncthreads();

    // GEMM thread tile: 8 m x 8 j per thread
    const int ty = tid >> 4, tx = tid & 15;
    const int m0 = ty * 8, j0 = tx * 8;

    unsigned long long acc[4][8];
#pragma unroll
    for (int p = 0; p < 4; p++)
#pragma unroll
        for (int j = 0; j < 8; j++) acc[p][j] = 0ull;

    // k-tiled mainloop
    for (int t = 0; t < HID / KT; t++) {
        const int kb = t * KT;

        // fill duplicated W2 tile: w2d[k][j] = (W2[kb+k][j], W2[kb+k][j])
#pragma unroll
        for (int i = tid; i < KT * 128; i += 256) {
            int j = i & 127, k = i >> 7;
            float w = W2[(kb + k) * 128 + j];
            w2d[k * 128 + j] = make_float2(w, w);
        }
        // fill h1 tile: h1t[k][m] = tanh(x*W1a[kb+k] + y*W1b[kb+k] + b1[kb+k])
#pragma unroll
        for (int i = tid; i < KT * 128; i += 256) {
            int m = i & 127, k = i >> 7;
            float pre = fmaf(sxv[m], sW1a[kb + k], fmaf(sy[m], sW1b[kb + k], sb1[kb + k]));
            h1t[k * 128 + m] = tanhf(pre);
        }
        __syncthreads();

#pragma unroll 4
        for (int k = 0; k < KT; k++) {
            const ulonglong2* ar = reinterpret_cast<const ulonglong2*>(&h1t[k * 128 + m0]);
            ulonglong2 A0 = ar[0], A1 = ar[1];
            unsigned long long av[4] = {A0.x, A0.y, A1.x, A1.y};

            const ulonglong2* br = reinterpret_cast<const ulonglong2*>(&w2d[k * 128 + j0]);
            ulonglong2 B0 = br[0], B1 = br[1], B2 = br[2], B3 = br[3];
            unsigned long long bv[8] = {B0.x, B0.y, B1.x, B1.y, B2.x, B2.y, B3.x, B3.y};

#pragma unroll
            for (int p = 0; p < 4; p++)
#pragma unroll
                for (int j = 0; j < 8; j++)
                    fma2(acc[p][j], av[p], bv[j]);
        }
        __syncthreads();   // tile buffers free for rewrite (and for 'red' alias after last tile)
    }

    // epilogue: h2 = tanh(c + b2); partial E = sum_j h2*W3  (red aliases dyn, safe post-sync)
#pragma unroll
    for (int p = 0; p < 4; p++) {
        float s_lo = 0.0f, s_hi = 0.0f;
#pragma unroll
        for (int j = 0; j < 8; j++) {
            float clo, chi;
            unpack2(acc[p][j], clo, chi);
            float h2lo = tanhf(clo + sb2[j0 + j]);
            float h2hi = tanhf(chi + sb2[j0 + j]);
            s_lo = fmaf(h2lo, sW3[j0 + j], s_lo);
            s_hi = fmaf(h2hi, sW3[j0 + j], s_hi);
        }
        red[(m0 + 2 * p) * 17 + tx]     = s_lo;
        red[(m0 + 2 * p + 1) * 17 + tx] = s_hi;
    }
    __syncthreads();

    if (tid < 128) {
        float e = 0.0f;
#pragma unroll
        for (int t = 0; t < 16; t++) e += red[tid * 17 + t];
        e += sb3;
        g_fx[g0 + tid] = e * e;
    }
}

// ---------------- per-row top-100 (exact top_k semantics: value then index) ----------------
__device__ __forceinline__ float block_reduce_512(float v, float* sred) {
    __syncthreads();
    const unsigned mask = 0xffffffffu;
#pragma unroll
    for (int o = 16; o > 0; o >>= 1) v += __shfl_down_sync(mask, v, o);
    int lane = threadIdx.x & 31, wid = threadIdx.x >> 5;
    if (lane == 0) sred[wid] = v;
    __syncthreads();
    if (wid == 0) {
        float r = (lane < 16) ? sred[lane] : 0.0f;
#pragma unroll
        for (int o = 8; o > 0; o >>= 1) r += __shfl_down_sync(mask, r, o);
        if (lane == 0) sred[16] = r;
    }
    __syncthreads();
    return sred[16];
}

__global__ void __launch_bounds__(512) topk_kernel() {
    __shared__ float skey[1024];
    __shared__ float syv[1024];
    __shared__ int   sidx[1024];
    __shared__ float sred[17];
    __shared__ float smu;

    const int tid = threadIdx.x;
    const int b   = blockIdx.x;
    const float* fx = g_fx + (size_t)b * CEM_S;
    const float* yy = g_y  + (size_t)b * CEM_S;

    for (int i = tid; i < 1024; i += 512) {
        if (i < CEM_S) { skey[i] = fx[i]; syv[i] = yy[i]; sidx[i] = i; }
        else           { skey[i] = __int_as_float(0x7f800000); syv[i] = 0.0f; sidx[i] = i; }
    }
    __syncthreads();

    // bitonic sort ascending by (key, idx)
    for (int k = 2; k <= 1024; k <<= 1) {
        for (int j = k >> 1; j > 0; j >>= 1) {
            for (int i = tid; i < 1024; i += 512) {
                int l = i ^ j;
                if (l > i) {
                    float ki = skey[i], kl = skey[l];
                    int ii = sidx[i], il = sidx[l];
                    bool gt  = (ki > kl) || (ki == kl && ii > il);
                    bool asc = ((i & k) == 0);
                    if (gt == asc) {
                        skey[i] = kl; skey[l] = ki;
                        sidx[i] = il; sidx[l] = ii;
                        float t = syv[i]; syv[i] = syv[l]; syv[l] = t;
                    }
                }
            }
            __syncthreads();
        }
    }

    // mean over 100 elites
    float v = (tid < CEM_NE) ? syv[tid] : 0.0f;
    float tot = block_reduce_512(v, sred);
    if (tid == 0) smu = tot / (float)CEM_NE;
    __syncthreads();
    float mu = smu;

    float d  = (tid < CEM_NE) ? (syv[tid] - mu) : 0.0f;
    float ss = block_reduce_512(d * d, sred);
    if (tid == 0) {
        g_mu[b]    = mu;
        g_sigma[b] = sqrtf(ss / (float)CEM_NE);
    }
}

// ---------------- final: yhat + diag-Gaussian samples ----------------
__global__ void sample_kernel(uint32_t k0, uint32_t k1, float* __restrict__ out) {
    int gid = blockIdx.x * blockDim.x + threadIdx.x;
    if (gid >= TOTAL) return;
    int b = gid & (NBATCH - 1);                 // flat (NS, NB): gid = s*NB + b
    float eps = bits_to_normal(tf_bits32(k0, k1, (uint32_t)gid));
    float mu = g_mu[b], sg = g_sigma[b];
    float cov = sg * sg;                         // TEMP = 1.0
    cov = fminf(fmaxf(cov, 1e-3f), 100.0f);
    out[NBATCH + gid] = mu + sqrtf(cov) * eps;
    if (gid < NBATCH) out[gid] = g_mu[gid];      // yhat
}

// ---------------- launch ----------------
extern "C" void kernel_launch(void* const* d_in, const int* in_sizes, int n_in,
                              void* d_out, int out_size)
{
    const float* x  = (const float*)d_in[0];
    const float* W1 = (const float*)d_in[1];
    const float* b1 = (const float*)d_in[2];
    const float* W2 = (const float*)d_in[3];
    const float* b2 = (const float*)d_in[4];
    const float* W3 = (const float*)d_in[5];
    const float* b3 = (const float*)d_in[6];
    float* out = (float*)d_out;

    // ---- JAX partitionable-mode key derivation ----
    uint32_t cem0 = 0u, cem1 = 0u; threefry2x32(0u, 42u, cem0, cem1);   // counter (0,0) -> k_cem
    uint32_t smp0 = 0u, smp1 = 1u; threefry2x32(0u, 42u, smp0, smp1);   // counter (0,1) -> k_samp

    uint32_t ik0[CEM_NI], ik1[CEM_NI];
    for (int i = 0; i < CEM_NI; i++) {
        uint32_t a = 0u, c = (uint32_t)i;
        threefry2x32(cem0, cem1, a, c);
        ik0[i] = a; ik1[i] = c;
    }

    const int SMEM_BYTES = 3 * KT * HID * (int)sizeof(float);   // 48KB (32KB w2d + 16KB h1t)
    cudaFuncSetAttribute(energy_kernel, cudaFuncAttributeMaxDynamicSharedMemorySize, SMEM_BYTES);

    init_kernel<<<(NBATCH + 255) / 256, 256>>>();

    for (int i = 0; i < CEM_NI; i++) {
        energy_kernel<<<TOTAL / 128, 256, SMEM_BYTES>>>(ik0[i], ik1[i], x, W1, b1, W2, b2, W3, b3);
        topk_kernel<<<NBATCH, 512>>>();
    }

    sample_kernel<<<(TOTAL + 255) / 256, 256>>>(smp0, smp1, out);
}

// round 4
// speedup vs baseline: 2.1463x; 2.1463x over previous
#include <cuda_runtime.h>
#include <cstdint>

#define NBATCH   2048
#define CEM_S    1000
#define CEM_NE   100
#define CEM_NI   10
#define HID      128
#define KT       32                   // k-tile for smem
#define TOTAL    (NBATCH * CEM_S)     // 2,048,000
#define INIT_SIG 10.0f

// ---------------- device scratch (no allocations allowed) ----------------
__device__ float g_mu[NBATCH];
__device__ float g_sigma[NBATCH];
__device__ float g_y[TOTAL];
__device__ float g_fx[TOTAL];

// ---------------- threefry-2x32 (exact JAX) ----------------
static __host__ __device__ __forceinline__ uint32_t rotl32(uint32_t v, uint32_t d) {
    return (v << d) | (v >> (32u - d));
}

static __host__ __device__ __forceinline__ void threefry2x32(
    uint32_t k0, uint32_t k1, uint32_t& x0, uint32_t& x1)
{
    uint32_t ks0 = k0, ks1 = k1, ks2 = k0 ^ k1 ^ 0x1BD11BDAu;
    x0 += ks0; x1 += ks1;
#define TF_R(r) { x0 += x1; x1 = rotl32(x1, r); x1 ^= x0; }
    TF_R(13) TF_R(15) TF_R(26) TF_R(6)   x0 += ks1; x1 += ks2 + 1u;
    TF_R(17) TF_R(29) TF_R(16) TF_R(24)  x0 += ks2; x1 += ks0 + 2u;
    TF_R(13) TF_R(15) TF_R(26) TF_R(6)   x0 += ks0; x1 += ks1 + 3u;
    TF_R(17) TF_R(29) TF_R(16) TF_R(24)  x0 += ks1; x1 += ks2 + 4u;
    TF_R(13) TF_R(15) TF_R(26) TF_R(6)   x0 += ks2; x1 += ks0 + 5u;
#undef TF_R
}

// partitionable-mode random bits for 32-bit: element i -> XOR-fold of cipher pair
__device__ __forceinline__ uint32_t tf_bits32(uint32_t k0, uint32_t k1, uint32_t idx) {
    uint32_t x0 = 0u, x1 = idx;     // counter = uint64 idx (hi=0 for idx < 2^32)
    threefry2x32(k0, k1, x0, x1);
    return x0 ^ x1;
}

// bits -> standard normal, matching jax.random.normal (uniform(-1+ulp,1) -> sqrt2*erfinv)
__device__ __forceinline__ float bits_to_normal(uint32_t bits) {
    float f = __uint_as_float((bits >> 9) | 0x3f800000u) - 1.0f;   // [0,1)
    const float lo = -0.99999994f;                                  // nextafter(-1,0)
    float u = fmaxf(lo, f * 2.0f + lo);                             // (hi-lo) rounds to 2.0f
    // XLA ErfInv f32 polynomial
    float w = -log1pf(-u * u);
    float p;
    if (w < 5.0f) {
        w -= 2.5f;
        p = 2.81022636e-08f;
        p = fmaf(p, w, 3.43273939e-07f);
        p = fmaf(p, w, -3.5233877e-06f);
        p = fmaf(p, w, -4.39150654e-06f);
        p = fmaf(p, w, 0.00021858087f);
        p = fmaf(p, w, -0.00125372503f);
        p = fmaf(p, w, -0.00417768164f);
        p = fmaf(p, w, 0.246640727f);
        p = fmaf(p, w, 1.50140941f);
    } else {
        w = sqrtf(w) - 3.0f;
        p = -0.000200214257f;
        p = fmaf(p, w, 0.000100950558f);
        p = fmaf(p, w, 0.00134934322f);
        p = fmaf(p, w, -0.00367342844f);
        p = fmaf(p, w, 0.00573950773f);
        p = fmaf(p, w, -0.0076224613f);
        p = fmaf(p, w, 0.00943887047f);
        p = fmaf(p, w, 1.00167406f);
        p = fmaf(p, w, 2.83297682f);
    }
    return 1.4142135623730951f * (p * u);   // float32(sqrt(2)) * erfinv(u)
}

// ---------------- packed f32x2 helpers ----------------
__device__ __forceinline__ void unpack2(unsigned long long v, float& lo, float& hi) {
    asm("mov.b64 {%0, %1}, %2;" : "=f"(lo), "=f"(hi) : "l"(v));
}
__device__ __forceinline__ void fma2(unsigned long long& d, unsigned long long a, unsigned long long b) {
    asm("fma.rn.f32x2 %0, %1, %2, %0;" : "+l"(d) : "l"(a), "l"(b));
}

// ---------------- init ----------------
__global__ void init_kernel() {
    int i = blockIdx.x * blockDim.x + threadIdx.x;
    if (i < NBATCH) { g_mu[i] = 0.0f; g_sigma[i] = INIT_SIG; }
}

// ---------------- fused sample + energy kernel ----------------
// One block = 128 candidates. 256 threads, 2 CTAs/SM.
// Dynamic smem (48KB): h1d = KT x 128 duplicated (a,a) float2 (32KB), W2s = KT x 128 plain (16KB).
// A loads are warp-broadcast (conflict-free); B loads are natural adjacent-j pairs (2-way max).
// 'red' (128x17 floats) aliases the dynamic buffer after the GEMM completes.
__global__ void __launch_bounds__(256, 2) energy_kernel(
    uint32_t k0, uint32_t k1,
    const float* __restrict__ x,  const float* __restrict__ W1, const float* __restrict__ b1,
    const float* __restrict__ W2, const float* __restrict__ b2,
    const float* __restrict__ W3, const float* __restrict__ b3)
{
    extern __shared__ float dyn[];
    float2* h1d = reinterpret_cast<float2*>(dyn);       // [KT*128] (a,a) pairs
    float*  W2s = dyn + 2 * KT * 128;                   // [KT*128] : W2s[k][j]
    float*  red = dyn;                                  // alias post-GEMM: [128][17]

    __shared__ float sy[128], sxv[128];
    __shared__ float sW1a[HID], sW1b[HID], sb1[HID], sb2[HID], sW3[HID];
    __shared__ float sb3;

    const int tid = threadIdx.x;
    const int g0  = blockIdx.x * 128;

    // stage small weights
    if (tid < HID) {
        sW1a[tid] = W1[tid];
        sW1b[tid] = W1[HID + tid];
        sb1[tid]  = b1[tid];
        sb2[tid]  = b2[tid];
        sW3[tid]  = W3[tid];
    }
    if (tid == 0) sb3 = b3[0];

    // generate candidates: eps via threefry (partitionable), Ys = mu + sigma*eps
    if (tid < 128) {
        int g = g0 + tid;                   // flat (NB, CEM_S) row-major index
        int b = g / CEM_S;
        float eps = bits_to_normal(tf_bits32(k0, k1, (uint32_t)g));
        float yv  = g_mu[b] + g_sigma[b] * eps;
        sy[tid]  = yv;
        sxv[tid] = x[b];
        g_y[g]   = yv;
    }
    __syncthreads();

    // GEMM thread tile: 8 m x 8 j per thread; acc packed along j (adjacent pairs)
    const int ty = tid >> 4, tx = tid & 15;
    const int m0 = ty * 8, j0 = tx * 8;

    unsigned long long acc[8][4];
#pragma unroll
    for (int m = 0; m < 8; m++)
#pragma unroll
        for (int jp = 0; jp < 4; jp++) acc[m][jp] = 0ull;

    // k-tiled mainloop
    for (int t = 0; t < HID / KT; t++) {
        const int kb = t * KT;

        // fill duplicated h1 tile: h1d[k][m] = (v, v), v = tanh(x*W1a + y*W1b + b1)
#pragma unroll
        for (int i = tid; i < KT * 128; i += 256) {
            int m = i & 127, k = i >> 7;
            float pre = fmaf(sxv[m], sW1a[kb + k], fmaf(sy[m], sW1b[kb + k], sb1[kb + k]));
            float v = tanhf(pre);
            h1d[k * 128 + m] = make_float2(v, v);
        }
        // fill plain W2 tile
#pragma unroll
        for (int i = tid; i < KT * 128; i += 256) {
            W2s[i] = W2[kb * 128 + i];
        }
        __syncthreads();

#pragma unroll 4
        for (int k = 0; k < KT; k++) {
            // A: 8 duplicated pairs (64B), warp-broadcast, conflict-free
            const ulonglong2* ad = reinterpret_cast<const ulonglong2*>(&h1d[k * 128 + m0]);
            ulonglong2 A0 = ad[0], A1 = ad[1], A2 = ad[2], A3 = ad[3];
            unsigned long long av[8] = {A0.x, A0.y, A1.x, A1.y, A2.x, A2.y, A3.x, A3.y};

            // B: 8 natural w values = 4 adjacent-j pairs (32B)
            const ulonglong2* br = reinterpret_cast<const ulonglong2*>(&W2s[k * 128 + j0]);
            ulonglong2 B0 = br[0], B1 = br[1];
            unsigned long long bv[4] = {B0.x, B0.y, B1.x, B1.y};

#pragma unroll
            for (int m = 0; m < 8; m++)
#pragma unroll
                for (int jp = 0; jp < 4; jp++)
                    fma2(acc[m][jp], av[m], bv[jp]);
        }
        __syncthreads();   // tile buffers free for rewrite (and for 'red' alias after last tile)
    }

    // epilogue: h2 = tanh(c + b2); partial E = sum_j h2*W3  (red aliases dyn, safe post-sync)
#pragma unroll
    for (int m = 0; m < 8; m++) {
        float s = 0.0f;
#pragma unroll
        for (int jp = 0; jp < 4; jp++) {
            float clo, chi;
            unpack2(acc[m][jp], clo, chi);
            float h2lo = tanhf(clo + sb2[j0 + 2 * jp]);
            float h2hi = tanhf(chi + sb2[j0 + 2 * jp + 1]);
            s = fmaf(h2lo, sW3[j0 + 2 * jp], s);
            s = fmaf(h2hi, sW3[j0 + 2 * jp + 1], s);
        }
        red[(m0 + m) * 17 + tx] = s;
    }
    __syncthreads();

    if (tid < 128) {
        float e = 0.0f;
#pragma unroll
        for (int t = 0; t < 16; t++) e += red[tid * 17 + t];
        e += sb3;
        g_fx[g0 + tid] = e * e;
    }
}

// ---------------- per-row top-100 (exact top_k semantics: value then index) ----------------
__device__ __forceinline__ float block_reduce_512(float v, float* sred) {
    __syncthreads();
    const unsigned mask = 0xffffffffu;
#pragma unroll
    for (int o = 16; o > 0; o >>= 1) v += __shfl_down_sync(mask, v, o);
    int lane = threadIdx.x & 31, wid = threadIdx.x >> 5;
    if (lane == 0) sred[wid] = v;
    __syncthreads();
    if (wid == 0) {
        float r = (lane < 16) ? sred[lane] : 0.0f;
#pragma unroll
        for (int o = 8; o > 0; o >>= 1) r += __shfl_down_sync(mask, r, o);
        if (lane == 0) sred[16] = r;
    }
    __syncthreads();
    return sred[16];
}

__global__ void __launch_bounds__(512) topk_kernel() {
    __shared__ float skey[1024];
    __shared__ float syv[1024];
    __shared__ int   sidx[1024];
    __shared__ float sred[17];
    __shared__ float smu;

    const int tid = threadIdx.x;
    const int b   = blockIdx.x;
    const float* fx = g_fx + (size_t)b * CEM_S;
    const float* yy = g_y  + (size_t)b * CEM_S;

    for (int i = tid; i < 1024; i += 512) {
        if (i < CEM_S) { skey[i] = fx[i]; syv[i] = yy[i]; sidx[i] = i; }
        else           { skey[i] = __int_as_float(0x7f800000); syv[i] = 0.0f; sidx[i] = i; }
    }
    __syncthreads();

    // bitonic sort ascending by (key, idx)
    for (int k = 2; k <= 1024; k <<= 1) {
        for (int j = k >> 1; j > 0; j >>= 1) {
            for (int i = tid; i < 1024; i += 512) {
                int l = i ^ j;
                if (l > i) {
                    float ki = skey[i], kl = skey[l];
                    int ii = sidx[i], il = sidx[l];
                    bool gt  = (ki > kl) || (ki == kl && ii > il);
                    bool asc = ((i & k) == 0);
                    if (gt == asc) {
                        skey[i] = kl; skey[l] = ki;
                        sidx[i] = il; sidx[l] = ii;
                        float t = syv[i]; syv[i] = syv[l]; syv[l] = t;
                    }
                }
            }
            __syncthreads();
        }
    }

    // mean over 100 elites
    float v = (tid < CEM_NE) ? syv[tid] : 0.0f;
    float tot = block_reduce_512(v, sred);
    if (tid == 0) smu = tot / (float)CEM_NE;
    __syncthreads();
    float mu = smu;

    float d  = (tid < CEM_NE) ? (syv[tid] - mu) : 0.0f;
    float ss = block_reduce_512(d * d, sred);
    if (tid == 0) {
        g_mu[b]    = mu;
        g_sigma[b] = sqrtf(ss / (float)CEM_NE);
    }
}

// ---------------- final: yhat + diag-Gaussian samples ----------------
__global__ void sample_kernel(uint32_t k0, uint32_t k1, float* __restrict__ out) {
    int gid = blockIdx.x * blockDim.x + threadIdx.x;
    if (gid >= TOTAL) return;
    int b = gid & (NBATCH - 1);                 // flat (NS, NB): gid = s*NB + b
    float eps = bits_to_normal(tf_bits32(k0, k1, (uint32_t)gid));
    float mu = g_mu[b], sg = g_sigma[b];
    float cov = sg * sg;                         // TEMP = 1.0
    cov = fminf(fmaxf(cov, 1e-3f), 100.0f);
    out[NBATCH + gid] = mu + sqrtf(cov) * eps;
    if (gid < NBATCH) out[gid] = g_mu[gid];      // yhat
}

// ---------------- launch ----------------
extern "C" void kernel_launch(void* const* d_in, const int* in_sizes, int n_in,
                              void* d_out, int out_size)
{
    const float* x  = (const float*)d_in[0];
    const float* W1 = (const float*)d_in[1];
    const float* b1 = (const float*)d_in[2];
    const float* W2 = (const float*)d_in[3];
    const float* b2 = (const float*)d_in[4];
    const float* W3 = (const float*)d_in[5];
    const float* b3 = (const float*)d_in[6];
    float* out = (float*)d_out;

    // ---- JAX partitionable-mode key derivation ----
    uint32_t cem0 = 0u, cem1 = 0u; threefry2x32(0u, 42u, cem0, cem1);   // counter (0,0) -> k_cem
    uint32_t smp0 = 0u, smp1 = 1u; threefry2x32(0u, 42u, smp0, smp1);   // counter (0,1) -> k_samp

    uint32_t ik0[CEM_NI], ik1[CEM_NI];
    for (int i = 0; i < CEM_NI; i++) {
        uint32_t a = 0u, c = (uint32_t)i;
        threefry2x32(cem0, cem1, a, c);
        ik0[i] = a; ik1[i] = c;
    }

    const int SMEM_BYTES = 3 * KT * HID * (int)sizeof(float);   // 48KB (32KB h1d + 16KB W2s)
    cudaFuncSetAttribute(energy_kernel, cudaFuncAttributeMaxDynamicSharedMemorySize, SMEM_BYTES);

    init_kernel<<<(NBATCH + 255) / 256, 256>>>();

    for (int i = 0; i < CEM_NI; i++) {
        energy_kernel<<<TOTAL / 128, 256, SMEM_BYTES>>>(ik0[i], ik1[i], x, W1, b1, W2, b2, W3, b3);
        topk_kernel<<<NBATCH, 512>>>();
    }

    sample_kernel<<<(TOTAL + 255) / 256, 256>>>(smp0, smp1, out);
}

// round 6
// speedup vs baseline: 2.2088x; 1.0291x over previous
#include <cuda_runtime.h>
#include <cstdint>

#define NBATCH   2048
#define CEM_S    1000
#define CEM_NE   100
#define CEM_NI   10
#define HID      128
#define KT       64                   // k-tile for smem
#define TOTAL    (NBATCH * CEM_S)     // 2,048,000
#define INIT_SIG 10.0f

// ---------------- device scratch (no allocations allowed) ----------------
__device__ float g_mu[NBATCH];
__device__ float g_sigma[NBATCH];
__device__ float g_y[TOTAL];
__device__ float g_fx[TOTAL];

// ---------------- threefry-2x32 (exact JAX, partitionable mode) ----------------
static __host__ __device__ __forceinline__ uint32_t rotl32(uint32_t v, uint32_t d) {
    return (v << d) | (v >> (32u - d));
}

static __host__ __device__ __forceinline__ void threefry2x32(
    uint32_t k0, uint32_t k1, uint32_t& x0, uint32_t& x1)
{
    uint32_t ks0 = k0, ks1 = k1, ks2 = k0 ^ k1 ^ 0x1BD11BDAu;
    x0 += ks0; x1 += ks1;
#define TF_R(r) { x0 += x1; x1 = rotl32(x1, r); x1 ^= x0; }
    TF_R(13) TF_R(15) TF_R(26) TF_R(6)   x0 += ks1; x1 += ks2 + 1u;
    TF_R(17) TF_R(29) TF_R(16) TF_R(24)  x0 += ks2; x1 += ks0 + 2u;
    TF_R(13) TF_R(15) TF_R(26) TF_R(6)   x0 += ks0; x1 += ks1 + 3u;
    TF_R(17) TF_R(29) TF_R(16) TF_R(24)  x0 += ks1; x1 += ks2 + 4u;
    TF_R(13) TF_R(15) TF_R(26) TF_R(6)   x0 += ks2; x1 += ks0 + 5u;
#undef TF_R
}

__device__ __forceinline__ uint32_t tf_bits32(uint32_t k0, uint32_t k1, uint32_t idx) {
    uint32_t x0 = 0u, x1 = idx;
    threefry2x32(k0, k1, x0, x1);
    return x0 ^ x1;
}

__device__ __forceinline__ float bits_to_normal(uint32_t bits) {
    float f = __uint_as_float((bits >> 9) | 0x3f800000u) - 1.0f;   // [0,1)
    const float lo = -0.99999994f;
    float u = fmaxf(lo, f * 2.0f + lo);
    float w = -log1pf(-u * u);
    float p;
    if (w < 5.0f) {
        w -= 2.5f;
        p = 2.81022636e-08f;
        p = fmaf(p, w, 3.43273939e-07f);
        p = fmaf(p, w, -3.5233877e-06f);
        p = fmaf(p, w, -4.39150654e-06f);
        p = fmaf(p, w, 0.00021858087f);
        p = fmaf(p, w, -0.00125372503f);
        p = fmaf(p, w, -0.00417768164f);
        p = fmaf(p, w, 0.246640727f);
        p = fmaf(p, w, 1.50140941f);
    } else {
        w = sqrtf(w) - 3.0f;
        p = -0.000200214257f;
        p = fmaf(p, w, 0.000100950558f);
        p = fmaf(p, w, 0.00134934322f);
        p = fmaf(p, w, -0.00367342844f);
        p = fmaf(p, w, 0.00573950773f);
        p = fmaf(p, w, -0.0076224613f);
        p = fmaf(p, w, 0.00943887047f);
        p = fmaf(p, w, 1.00167406f);
        p = fmaf(p, w, 2.83297682f);
    }
    return 1.4142135623730951f * (p * u);
}

// ---------------- packed f32x2 helpers ----------------
__device__ __forceinline__ unsigned long long pack2(float lo, float hi) {
    unsigned long long r;
    asm("mov.b64 %0, {%1, %2};" : "=l"(r) : "f"(lo), "f"(hi));
    return r;
}
__device__ __forceinline__ void unpack2(unsigned long long v, float& lo, float& hi) {
    asm("mov.b64 {%0, %1}, %2;" : "=f"(lo), "=f"(hi) : "l"(v));
}
__device__ __forceinline__ unsigned long long swap2(unsigned long long v) {
    float lo, hi; unpack2(v, lo, hi);
    return pack2(hi, lo);
}
__device__ __forceinline__ void fma2(unsigned long long& d, unsigned long long a, unsigned long long b) {
    asm("fma.rn.f32x2 %0, %1, %2, %0;" : "+l"(d) : "l"(a), "l"(b));
}

// ---------------- init ----------------
__global__ void init_kernel() {
    int i = blockIdx.x * blockDim.x + threadIdx.x;
    if (i < NBATCH) { g_mu[i] = 0.0f; g_sigma[i] = INIT_SIG; }
}

// ---------------- fused sample + energy kernel ----------------
// One block = 128 candidates. 128 threads, 2 CTAs/SM.
// Per-thread tile: 16 m x 8 j. No operand duplication: A natural m-pairs, B natural
// j-pairs + lane-swapped copies (2 FMA2 per pair-pair gives all 4 products).
// Dynamic smem (64KB): h1t[KT][128] (32KB) + W2s[KT][128] (32KB). 'red' aliases post-GEMM.
__global__ void __launch_bounds__(128, 2) energy_kernel(
    uint32_t k0, uint32_t k1,
    const float* __restrict__ x,  const float* __restrict__ W1, const float* __restrict__ b1,
    const float* __restrict__ W2, const float* __restrict__ b2,
    const float* __restrict__ W3, const float* __restrict__ b3)
{
    extern __shared__ float dyn[];
    float* h1t = dyn;                   // [KT*128] : h1t[k][m]
    float* W2s = dyn + KT * 128;        // [KT*128] : W2s[k][j]
    float* red = dyn;                   // alias post-GEMM: [128][17]

    __shared__ float sy[128], sxv[128];
    __shared__ float sW1a[HID], sW1b[HID], sb1[HID], sb2[HID], sW3[HID];
    __shared__ float sb3;

    const int tid = threadIdx.x;
    const int g0  = blockIdx.x * 128;

    // stage small weights
    if (tid < HID) {
        sW1a[tid] = W1[tid];
        sW1b[tid] = W1[HID + tid];
        sb1[tid]  = b1[tid];
        sb2[tid]  = b2[tid];
        sW3[tid]  = W3[tid];
    }
    if (tid == 0) sb3 = b3[0];

    // candidates: eps via threefry (partitionable), Ys = mu + sigma*eps
    {
        int g = g0 + tid;
        int b = g / CEM_S;
        float eps = bits_to_normal(tf_bits32(k0, k1, (uint32_t)g));
        float yv  = g_mu[b] + g_sigma[b] * eps;
        sy[tid]  = yv;
        sxv[tid] = x[b];
        g_y[g]   = yv;
    }
    __syncthreads();

    // thread tile: 16 m x 8 j
    const int mg = tid >> 4, jg = tid & 15;
    const int m0 = mg * 16, j0 = jg * 8;

    unsigned long long accd[8][4];   // (c[m0+2p][j0+2q],   c[m0+2p+1][j0+2q+1])
    unsigned long long accs[8][4];   // (c[m0+2p][j0+2q+1], c[m0+2p+1][j0+2q])
#pragma unroll
    for (int p = 0; p < 8; p++)
#pragma unroll
        for (int q = 0; q < 4; q++) { accd[p][q] = 0ull; accs[p][q] = 0ull; }

    for (int t = 0; t < HID / KT; t++) {
        const int kb = t * KT;

        // fill W2 tile (coalesced float4)
        {
            const float4* gw = reinterpret_cast<const float4*>(W2 + kb * 128);
            float4* sw = reinterpret_cast<float4*>(W2s);
#pragma unroll
            for (int i = tid; i < KT * 32; i += 128) sw[i] = gw[i];
        }
        // fill h1 tile: h1t[k][m] = tanh(x*W1a + y*W1b + b1)
#pragma unroll
        for (int i = tid; i < KT * 128; i += 128) {
            int m = i & 127, k = i >> 7;
            float pre = fmaf(sxv[m], sW1a[kb + k], fmaf(sy[m], sW1b[kb + k], sb1[kb + k]));
            h1t[i] = tanhf(pre);
        }
        __syncthreads();

#pragma unroll 2
        for (int k = 0; k < KT; k++) {
            // A: 16 natural floats = 8 adjacent-m pairs (64B)
            const ulonglong2* ar = reinterpret_cast<const ulonglong2*>(&h1t[k * 128 + m0]);
            ulonglong2 A0 = ar[0], A1 = ar[1], A2 = ar[2], A3 = ar[3];
            unsigned long long av[8] = {A0.x, A0.y, A1.x, A1.y, A2.x, A2.y, A3.x, A3.y};

            // B: 8 natural floats = 4 adjacent-j pairs (32B) + swapped copies
            const ulonglong2* br = reinterpret_cast<const ulonglong2*>(&W2s[k * 128 + j0]);
            ulonglong2 B0 = br[0], B1 = br[1];
            unsigned long long bv[4] = {B0.x, B0.y, B1.x, B1.y};
            unsigned long long sv[4] = {swap2(bv[0]), swap2(bv[1]), swap2(bv[2]), swap2(bv[3])};

#pragma unroll
            for (int p = 0; p < 8; p++)
#pragma unroll
                for (int q = 0; q < 4; q++) {
                    fma2(accd[p][q], av[p], bv[q]);
                    fma2(accs[p][q], av[p], sv[q]);
                }
        }
        __syncthreads();   // tile buffers free for rewrite ('red' alias after last tile)
    }

    // epilogue: h2 = tanh(c + b2); partial E = sum_j h2*W3
#pragma unroll
    for (int p = 0; p < 8; p++) {
        float se = 0.0f, so = 0.0f;   // rows m0+2p (even), m0+2p+1 (odd)
#pragma unroll
        for (int q = 0; q < 4; q++) {
            float d_lo, d_hi, s_lo, s_hi;
            unpack2(accd[p][q], d_lo, d_hi);
            unpack2(accs[p][q], s_lo, s_hi);
            float b2e = sb2[j0 + 2 * q],     w3e = sW3[j0 + 2 * q];
            float b2o = sb2[j0 + 2 * q + 1], w3o = sW3[j0 + 2 * q + 1];
            se = fmaf(tanhf(d_lo + b2e), w3e, se);
            se = fmaf(tanhf(s_lo + b2o), w3o, se);
            so = fmaf(tanhf(s_hi + b2e), w3e, so);
            so = fmaf(tanhf(d_hi + b2o), w3o, so);
        }
        red[(m0 + 2 * p) * 17 + jg]     = se;
        red[(m0 + 2 * p + 1) * 17 + jg] = so;
    }
    __syncthreads();

    {
        float e = 0.0f;
#pragma unroll
        for (int t = 0; t < 16; t++) e += red[tid * 17 + t];
        e += sb3;
        g_fx[g0 + tid] = e * e;
    }
}

// ---------------- per-row top-100 (exact top_k semantics: value then index) ----------------
__device__ __forceinline__ float block_reduce_512(float v, float* sred) {
    __syncthreads();
    const unsigned mask = 0xffffffffu;
#pragma unroll
    for (int o = 16; o > 0; o >>= 1) v += __shfl_down_sync(mask, v, o);
    int lane = threadIdx.x & 31, wid = threadIdx.x >> 5;
    if (lane == 0) sred[wid] = v;
    __syncthreads();
    if (wid == 0) {
        float r = (lane < 16) ? sred[lane] : 0.0f;
#pragma unroll
        for (int o = 8; o > 0; o >>= 1) r += __shfl_down_sync(mask, r, o);
        if (lane == 0) sred[16] = r;
    }
    __syncthreads();
    return sred[16];
}

__global__ void __launch_bounds__(512) topk_kernel() {
    __shared__ float skey[1024];
    __shared__ float syv[1024];
    __shared__ int   sidx[1024];
    __shared__ float sred[17];
    __shared__ float smu;

    const int tid = threadIdx.x;
    const int b   = blockIdx.x;
    const float* fx = g_fx + (size_t)b * CEM_S;
    const float* yy = g_y  + (size_t)b * CEM_S;

    for (int i = tid; i < 1024; i += 512) {
        if (i < CEM_S) { skey[i] = fx[i]; syv[i] = yy[i]; sidx[i] = i; }
        else           { skey[i] = __int_as_float(0x7f800000); syv[i] = 0.0f; sidx[i] = i; }
    }
    __syncthreads();

    for (int k = 2; k <= 1024; k <<= 1) {
        for (int j = k >> 1; j > 0; j >>= 1) {
            for (int i = tid; i < 1024; i += 512) {
                int l = i ^ j;
                if (l > i) {
                    float ki = skey[i], kl = skey[l];
                    int ii = sidx[i], il = sidx[l];
                    bool gt  = (ki > kl) || (ki == kl && ii > il);
                    bool asc = ((i & k) == 0);
                    if (gt == asc) {
                        skey[i] = kl; skey[l] = ki;
                        sidx[i] = il; sidx[l] = ii;
                        float t = syv[i]; syv[i] = syv[l]; syv[l] = t;
                    }
                }
            }
            __syncthreads();
        }
    }

    float v = (tid < CEM_NE) ? syv[tid] : 0.0f;
    float tot = block_reduce_512(v, sred);
    if (tid == 0) smu = tot / (float)CEM_NE;
    __syncthreads();
    float mu = smu;

    float d  = (tid < CEM_NE) ? (syv[tid] - mu) : 0.0f;
    float ss = block_reduce_512(d * d, sred);
    if (tid == 0) {
        g_mu[b]    = mu;
        g_sigma[b] = sqrtf(ss / (float)CEM_NE);
    }
}

// ---------------- final: yhat + diag-Gaussian samples ----------------
__global__ void sample_kernel(uint32_t k0, uint32_t k1, float* __restrict__ out) {
    int gid = blockIdx.x * blockDim.x + threadIdx.x;
    if (gid >= TOTAL) return;
    int b = gid & (NBATCH - 1);
    float eps = bits_to_normal(tf_bits32(k0, k1, (uint32_t)gid));
    float mu = g_mu[b], sg = g_sigma[b];
    float cov = sg * sg;
    cov = fminf(fmaxf(cov, 1e-3f), 100.0f);
    out[NBATCH + gid] = mu + sqrtf(cov) * eps;
    if (gid < NBATCH) out[gid] = g_mu[gid];
}

// ---------------- launch ----------------
extern "C" void kernel_launch(void* const* d_in, const int* in_sizes, int n_in,
                              void* d_out, int out_size)
{
    const float* x  = (const float*)d_in[0];
    const float* W1 = (const float*)d_in[1];
    const float* b1 = (const float*)d_in[2];
    const float* W2 = (const float*)d_in[3];
    const float* b2 = (const float*)d_in[4];
    const float* W3 = (const float*)d_in[5];
    const float* b3 = (const float*)d_in[6];
    float* out = (float*)d_out;

    // JAX partitionable-mode key derivation
    uint32_t cem0 = 0u, cem1 = 0u; threefry2x32(0u, 42u, cem0, cem1);   // split(key,2)[0]
    uint32_t smp0 = 0u, smp1 = 1u; threefry2x32(0u, 42u, smp0, smp1);   // split(key,2)[1]

    uint32_t ik0[CEM_NI], ik1[CEM_NI];
    for (int i = 0; i < CEM_NI; i++) {
        uint32_t a = 0u, c = (uint32_t)i;
        threefry2x32(cem0, cem1, a, c);
        ik0[i] = a; ik1[i] = c;
    }

    const int SMEM_BYTES = 2 * KT * HID * (int)sizeof(float);   // 64KB
    cudaFuncSetAttribute(energy_kernel, cudaFuncAttributeMaxDynamicSharedMemorySize, SMEM_BYTES);

    init_kernel<<<(NBATCH + 255) / 256, 256>>>();

    for (int i = 0; i < CEM_NI; i++) {
        energy_kernel<<<TOTAL / 128, 128, SMEM_BYTES>>>(ik0[i], ik1[i], x, W1, b1, W2, b2, W3, b3);
        topk_kernel<<<NBATCH, 512>>>();
    }

    sample_kernel<<<(TOTAL + 255) / 256, 256>>>(smp0, smp1, out);
}